// round 8
// baseline (speedup 1.0000x reference)
#include <cuda_runtime.h>
#include <cstdint>

// Problem constants (fixed by the dataset)
#define Nn 8
#define Kk 16
#define Hh 256
#define Ww 256
#define Cc 4
#define Pp 100000
#define HW (Hh * Ww)          // 65536
#define NPIX (Nn * HW)        // 524288

// Scratch: ptclds transposed to AoS (P x float4) — __device__ global, no alloc.
__device__ float4 g_ptcld_aos[Pp];

// Kernel 1: transpose (C,P) -> AoS float4[P]
__global__ void transpose_ptcld_kernel(const float* __restrict__ ptclds) {
    int i = blockIdx.x * blockDim.x + threadIdx.x;
    if (i < Pp) {
        float4 v;
        v.x = ptclds[0 * Pp + i];
        v.y = ptclds[1 * Pp + i];
        v.z = ptclds[2 * Pp + i];
        v.w = ptclds[3 * Pp + i];
        g_ptcld_aos[i] = v;
    }
}

// 16-byte async copy global->shared (LDGSTS): bytes in flight WITHOUT registers.
__device__ __forceinline__ void cp_async16(void* smem_dst, const void* gmem_src) {
    uint32_t s = (uint32_t)__cvta_generic_to_shared(smem_dst);
    asm volatile("cp.async.cg.shared.global [%0], [%1], 16;\n"
                 :: "r"(s), "l"(gmem_src) : "memory");
}

// Kernel 2: block = 256 consecutive pixels. Stage the whole 32KB input tile
// (16 frag rows + 16 alpha rows) via cp.async — 32KB in flight per block,
// register-free — then composite from smem in 4-slot chunks with batched
// predicated L2 gathers and a chunk-granular z-sorted early break.
__global__ __launch_bounds__(256) void composite_kernel(
    const int*   __restrict__ fragments,   // (N,K,H,W)
    const float* __restrict__ alphas,      // (N,K,H,W)
    const float* __restrict__ background,  // (3,)
    float*       __restrict__ out)         // (N,C,H,W)
{
    __shared__ int   fragS [Kk * 256];
    __shared__ float alphaS[Kk * 256];

    const int t    = threadIdx.x;
    const int pix0 = blockIdx.x * 256;
    const int n    = pix0 >> 16;          // pix0 / HW
    const int hw0  = pix0 & (HW - 1);     // pix0 % HW
    const int base = n * (Kk * HW) + hw0;

    // ---- stage: 8 x 16B cp.async per thread (4 frag rows + 4 alpha rows) ----
    const int row   = t >> 6;             // 0..3
    const int col   = (t & 63) * 4;       // element offset (16B granularity)
    #pragma unroll
    for (int i = 0; i < 4; ++i) {
        int k = row + i * 4;
        cp_async16(&fragS[k * 256 + col], fragments + base + k * HW + col);
    }
    #pragma unroll
    for (int i = 0; i < 4; ++i) {
        int k = row + i * 4;
        cp_async16(&alphaS[k * 256 + col], alphas + base + k * HW + col);
    }
    asm volatile("cp.async.commit_group;\n" ::: "memory");
    asm volatile("cp.async.wait_group 0;\n" ::: "memory");
    __syncthreads();

    // ---- composite from smem, 4-slot chunks ----
    float T = 1.f, r = 0.f, g = 0.f, b = 0.f, acc = 0.f;
    int bg = 0;

    #pragma unroll 1
    for (int c = 0; c < 4; ++c) {
        const int kb = c * 4;
        // 4 LDS frag + 4 LDS alpha (lane-indexed -> conflict-free)
        int   f0 = fragS [(kb + 0) * 256 + t];
        int   f1 = fragS [(kb + 1) * 256 + t];
        int   f2 = fragS [(kb + 2) * 256 + t];
        int   f3 = fragS [(kb + 3) * 256 + t];
        float a0 = alphaS[(kb + 0) * 256 + t];
        float a1 = alphaS[(kb + 1) * 256 + t];
        float a2 = alphaS[(kb + 2) * 256 + t];
        float a3 = alphaS[(kb + 3) * 256 + t];

        // batched predicated gathers (independent L2 accesses)
        float4 p0, p1, p2, p3;
        if (f0 >= 0) p0 = g_ptcld_aos[f0];
        if (f1 >= 0) p1 = g_ptcld_aos[f1];
        if (f2 >= 0) p2 = g_ptcld_aos[f2];
        if (f3 >= 0) p3 = g_ptcld_aos[f3];

        if (c == 0) bg = (f0 < 0);

        if (f0 >= 0) {
            float w = a0 * T;  T *= (1.0f - a0);
            r = fmaf(w, p0.x, r); g = fmaf(w, p0.y, g);
            b = fmaf(w, p0.z, b); acc = fmaf(w, p0.w, acc);
        }
        if (f1 >= 0) {
            float w = a1 * T;  T *= (1.0f - a1);
            r = fmaf(w, p1.x, r); g = fmaf(w, p1.y, g);
            b = fmaf(w, p1.z, b); acc = fmaf(w, p1.w, acc);
        }
        if (f2 >= 0) {
            float w = a2 * T;  T *= (1.0f - a2);
            r = fmaf(w, p2.x, r); g = fmaf(w, p2.y, g);
            b = fmaf(w, p2.z, b); acc = fmaf(w, p2.w, acc);
        }
        if (f3 >= 0) {
            float w = a3 * T;  T *= (1.0f - a3);
            r = fmaf(w, p3.x, r); g = fmaf(w, p3.y, g);
            b = fmaf(w, p3.z, b); acc = fmaf(w, p3.w, acc);
        }

        // z-sorted: if last slot of this chunk is invalid, all later are too.
        if (f3 < 0) break;
    }

    if (bg) {
        r = background[0]; g = background[1]; b = background[2]; acc = 1.0f;
    }

    float* outp = out + n * (Cc * HW) + hw0 + t;
    outp[0 * HW] = r;
    outp[1 * HW] = g;
    outp[2 * HW] = b;
    outp[3 * HW] = acc;
}

extern "C" void kernel_launch(void* const* d_in, const int* in_sizes, int n_in,
                              void* d_out, int out_size) {
    const int*   fragments  = (const int*)  d_in[0];  // (N,K,H,W) int32
    const float* alphas     = (const float*)d_in[1];  // (N,K,H,W) f32
    const float* ptclds     = (const float*)d_in[2];  // (C,P) f32
    const float* background = (const float*)d_in[3];  // (3,) f32
    float* out = (float*)d_out;                       // (N,C,H,W) f32

    transpose_ptcld_kernel<<<(Pp + 255) / 256, 256>>>(ptclds);
    composite_kernel<<<NPIX / 256, 256>>>(fragments, alphas, background, out);
}

// round 9
// speedup vs baseline: 1.3727x; 1.3727x over previous
#include <cuda_runtime.h>

// Problem constants (fixed by the dataset)
#define Nn 8
#define Kk 16
#define Hh 256
#define Ww 256
#define Cc 4
#define Pp 100000
#define HW (Hh * Ww)          // 65536
#define NPIX (Nn * HW)        // 524288
#define ITER 4                // pixels per thread, software-pipelined

// Scratch: ptclds transposed to AoS (P x float4) — __device__ global, no alloc.
__device__ float4 g_ptcld_aos[Pp];

// Kernel 1: transpose (C,P) -> AoS float4[P]
__global__ void transpose_ptcld_kernel(const float* __restrict__ ptclds) {
    int i = blockIdx.x * blockDim.x + threadIdx.x;
    if (i < Pp) {
        float4 v;
        v.x = ptclds[0 * Pp + i];
        v.y = ptclds[1 * Pp + i];
        v.z = ptclds[2 * Pp + i];
        v.w = ptclds[3 * Pp + i];
        g_ptcld_aos[i] = v;
    }
}

// Kernel 2: ITER pixels per thread, register software pipeline:
// next pixel's 32 coalesced LDGs are issued BEFORE the current pixel's
// gathers+math, so DRAM latency hides under gather work and the L1tex
// queue is fed continuously (R7's phase-bursting was the bottleneck).
// No barriers, no smem — warps stay autonomous (R8 lesson).
__global__ __launch_bounds__(256, 2) void composite_kernel(
    const int*   __restrict__ fragments,   // (N,K,H,W)
    const float* __restrict__ alphas,      // (N,K,H,W)
    const float* __restrict__ background,  // (3,)
    float*       __restrict__ out)         // (N,C,H,W)
{
    const int t = threadIdx.x;
    int pix = blockIdx.x * (256 * ITER) + t;

    const float bgr = background[0];
    const float bgg = background[1];
    const float bgb = background[2];

    // ---- prologue: load pixel 0's inputs (32 independent coalesced LDGs) ----
    int   f[Kk];
    float a[Kk];
    {
        const int n  = pix >> 16;
        const int hw = pix & (HW - 1);
        const int base = n * (Kk * HW) + hw;
        #pragma unroll
        for (int k = 0; k < Kk; ++k) f[k] = fragments[base + k * HW];
        #pragma unroll
        for (int k = 0; k < Kk; ++k) a[k] = alphas[base + k * HW];
    }

    #pragma unroll
    for (int i = 0; i < ITER; ++i) {
        // ---- prefetch next pixel's inputs BEFORE consuming current ----
        int   fN[Kk];
        float aN[Kk];
        const int pixN = pix + 256;
        if (i < ITER - 1) {
            const int nN  = pixN >> 16;
            const int hwN = pixN & (HW - 1);
            const int baseN = nN * (Kk * HW) + hwN;
            #pragma unroll
            for (int k = 0; k < Kk; ++k) fN[k] = fragments[baseN + k * HW];
            #pragma unroll
            for (int k = 0; k < Kk; ++k) aN[k] = alphas[baseN + k * HW];
        }

        // ---- composite current pixel ----
        float T = 1.f, r = 0.f, g = 0.f, b = 0.f, acc = 0.f;

        {   // half 1: k = 0..7, gathers batched then math
            float4 p[8];
            #pragma unroll
            for (int j = 0; j < 8; ++j)
                if (f[j] >= 0) p[j] = g_ptcld_aos[f[j]];
            #pragma unroll
            for (int j = 0; j < 8; ++j) {
                if (f[j] >= 0) {
                    float w = a[j] * T;  T *= (1.0f - a[j]);
                    r   = fmaf(w, p[j].x, r);
                    g   = fmaf(w, p[j].y, g);
                    b   = fmaf(w, p[j].z, b);
                    acc = fmaf(w, p[j].w, acc);
                }
            }
        }

        // half 2: k = 8..15 — z-sorted: skip entirely if f[8] < 0
        if (f[8] >= 0) {
            float4 p[8];
            #pragma unroll
            for (int j = 0; j < 8; ++j)
                if (f[8 + j] >= 0) p[j] = g_ptcld_aos[f[8 + j]];
            #pragma unroll
            for (int j = 0; j < 8; ++j) {
                const int k = 8 + j;
                if (f[k] >= 0) {
                    float w = a[k] * T;  T *= (1.0f - a[k]);
                    r   = fmaf(w, p[j].x, r);
                    g   = fmaf(w, p[j].y, g);
                    b   = fmaf(w, p[j].z, b);
                    acc = fmaf(w, p[j].w, acc);
                }
            }
        }

        // background fill where no nearest point exists
        if (f[0] < 0) { r = bgr; g = bgg; b = bgb; acc = 1.0f; }

        // store (coalesced per channel)
        {
            const int n  = pix >> 16;
            const int hw = pix & (HW - 1);
            float* outp = out + n * (Cc * HW) + hw;
            outp[0 * HW] = r;
            outp[1 * HW] = g;
            outp[2 * HW] = b;
            outp[3 * HW] = acc;
        }

        // ---- rotate pipeline registers (renamed by unroll, no real MOVs) ----
        if (i < ITER - 1) {
            #pragma unroll
            for (int k = 0; k < Kk; ++k) { f[k] = fN[k]; a[k] = aN[k]; }
            pix = pixN;
        }
    }
}

extern "C" void kernel_launch(void* const* d_in, const int* in_sizes, int n_in,
                              void* d_out, int out_size) {
    const int*   fragments  = (const int*)  d_in[0];  // (N,K,H,W) int32
    const float* alphas     = (const float*)d_in[1];  // (N,K,H,W) f32
    const float* ptclds     = (const float*)d_in[2];  // (C,P) f32
    const float* background = (const float*)d_in[3];  // (3,) f32
    float* out = (float*)d_out;                       // (N,C,H,W) f32

    transpose_ptcld_kernel<<<(Pp + 255) / 256, 256>>>(ptclds);
    composite_kernel<<<NPIX / (256 * ITER), 256>>>(fragments, alphas, background, out);
}

// round 10
// speedup vs baseline: 1.6342x; 1.1905x over previous
#include <cuda_runtime.h>

// Problem constants (fixed by the dataset)
#define Nn 8
#define Kk 16
#define Hh 256
#define Ww 256
#define Cc 4
#define Pp 100000
#define HW (Hh * Ww)          // 65536
#define NPIX (Nn * HW)        // 524288
#define WEPS 2e-5f            // skip gathers whose compositing weight is negligible

// Scratch: ptclds transposed to AoS (P x float4) — __device__ global, no alloc.
__device__ float4 g_ptcld_aos[Pp];

// Kernel 1: transpose (C,P) -> AoS float4[P]
__global__ void transpose_ptcld_kernel(const float* __restrict__ ptclds) {
    int i = blockIdx.x * blockDim.x + threadIdx.x;
    if (i < Pp) {
        float4 v;
        v.x = ptclds[0 * Pp + i];
        v.y = ptclds[1 * Pp + i];
        v.z = ptclds[2 * Pp + i];
        v.w = ptclds[3 * Pp + i];
        g_ptcld_aos[i] = v;
    }
}

// Kernel 2: 1 thread/pixel. All 32 input LDGs batched; transmittance weights
// precomputed from alphas (serial T-chain overlaps the gather latency instead
// of sitting between gather batches); gathers predicated on weight > WEPS
// (kills both invalid slots AND negligible deep-tail slots -> fewer L1tex
// wavefronts); post-gather math is 4 independent FMA chains.
__global__ __launch_bounds__(256, 3) void composite_kernel(
    const int*   __restrict__ fragments,   // (N,K,H,W)
    const float* __restrict__ alphas,      // (N,K,H,W)
    const float* __restrict__ background,  // (3,)
    float*       __restrict__ out)         // (N,C,H,W)
{
    const int pix = blockIdx.x * blockDim.x + threadIdx.x;
    const int n  = pix >> 16;          // pix / HW
    const int hw = pix & (HW - 1);     // pix % HW

    const int base = n * (Kk * HW) + hw;
    float* outp = out + n * (Cc * HW) + hw;

    // Batch 1: 16 fragment loads (gather addresses depend on these).
    int f[Kk];
    #pragma unroll
    for (int k = 0; k < Kk; ++k) f[k] = fragments[base + k * HW];

    // Batch 2: 16 alpha loads — independent, in flight alongside batch 1.
    float w[Kk];
    #pragma unroll
    for (int k = 0; k < Kk; ++k) w[k] = alphas[base + k * HW];

    // Precompute compositing weights in place: w[k] = a_k * prod_{j<k}(1-a_j),
    // with invalid slots contributing a=0 (w=0, T unchanged). This serial
    // chain runs as soon as alphas land — overlapped with nothing downstream.
    {
        float T = 1.0f;
        #pragma unroll
        for (int k = 0; k < Kk; ++k) {
            const bool valid = (f[k] >= 0);
            const float a = valid ? w[k] : 0.0f;
            w[k] = a * T;
            T = T - a * T;              // T *= (1 - a), single FFMA
        }
    }

    float r = 0.f, g = 0.f, b = 0.f, acc = 0.f;

    // ---- half 1: k = 0..7 : weight-predicated gathers batched, then FMAs ----
    {
        float4 p[8];
        #pragma unroll
        for (int j = 0; j < 8; ++j)
            if (w[j] > WEPS) p[j] = g_ptcld_aos[f[j]];
        #pragma unroll
        for (int j = 0; j < 8; ++j) {
            if (w[j] > WEPS) {
                r   = fmaf(w[j], p[j].x, r);
                g   = fmaf(w[j], p[j].y, g);
                b   = fmaf(w[j], p[j].z, b);
                acc = fmaf(w[j], p[j].w, acc);
            }
        }
    }

    // ---- half 2: k = 8..15 (skip if z-sorted sentinel or negligible tail) ----
    if (f[8] >= 0 && w[8] > WEPS) {
        float4 p[8];
        #pragma unroll
        for (int j = 0; j < 8; ++j)
            if (w[8 + j] > WEPS) p[j] = g_ptcld_aos[f[8 + j]];
        #pragma unroll
        for (int j = 0; j < 8; ++j) {
            const int k = 8 + j;
            if (w[k] > WEPS) {
                r   = fmaf(w[k], p[j].x, r);
                g   = fmaf(w[k], p[j].y, g);
                b   = fmaf(w[k], p[j].z, b);
                acc = fmaf(w[k], p[j].w, acc);
            }
        }
    }

    // Background fill where no nearest point exists
    if (f[0] < 0) {
        r = background[0]; g = background[1]; b = background[2]; acc = 1.0f;
    }

    outp[0 * HW] = r;
    outp[1 * HW] = g;
    outp[2 * HW] = b;
    outp[3 * HW] = acc;
}

extern "C" void kernel_launch(void* const* d_in, const int* in_sizes, int n_in,
                              void* d_out, int out_size) {
    const int*   fragments  = (const int*)  d_in[0];  // (N,K,H,W) int32
    const float* alphas     = (const float*)d_in[1];  // (N,K,H,W) f32
    const float* ptclds     = (const float*)d_in[2];  // (C,P) f32
    const float* background = (const float*)d_in[3];  // (3,) f32
    float* out = (float*)d_out;                       // (N,C,H,W) f32

    transpose_ptcld_kernel<<<(Pp + 255) / 256, 256>>>(ptclds);
    composite_kernel<<<NPIX / 256, 256>>>(fragments, alphas, background, out);
}